// round 9
// baseline (speedup 1.0000x reference)
#include <cuda_runtime.h>

// Reverse cummax along axis 1 of [B=16, H=128, W=128, C=256] float32.
// out[b,h,w,c] = max over h' >= h of in[b,h',w,c].
//
// R4 dataflow (re-bench after infra failure): interleaved load-prefetch +
// max + store ring, D=8 (the best-profiled structure, DRAM 75.9% in R2) with:
//  - chunk-relative constant offsets: one pointer decrement of 8*HS per chunk,
//    the 8 loads/stores use compile-time immediate offsets (|off| <= 1MB fits
//    the 24-bit signed SASS immediate) -> fewer regs, less ALU.
//  - 64-thread blocks (2048 blocks) for finer per-SM balance.

#define B 16
#define H 128
#define HS 8192               // h-stride in float4 (W*C/4)
#define NCOLS (B * HS)        // 131072 columns
#define D 8                   // ring depth
#define NCHUNK (H / D)        // 16

__device__ __forceinline__ float4 fmax4(float4 a, float4 b) {
    float4 r;
    r.x = fmaxf(a.x, b.x);
    r.y = fmaxf(a.y, b.y);
    r.z = fmaxf(a.z, b.z);
    r.w = fmaxf(a.w, b.w);
    return r;
}

__global__ __launch_bounds__(64) void revcummax_kernel(
    const float4* __restrict__ in, float4* __restrict__ out) {
    int idx = blockIdx.x * blockDim.x + threadIdx.x;

    int b = idx >> 13;           // / HS
    int inner = idx & (HS - 1);
    long long base = (long long)b * H * (long long)HS + inner;

    // Cursors point at the TOP of the current chunk (highest h of the chunk).
    const float4* pl = in + base + (H - 1) * (long long)HS;
    float4* q = out + base + (H - 1) * (long long)HS;

    // Prologue: fill the ring with h = H-1 .. H-D (immediate offsets).
    float4 v[D];
#pragma unroll
    for (int i = 0; i < D; i++)
        v[i] = __ldcs(pl - (long long)i * HS);
    pl -= (long long)D * HS;

    float4 m;
    m.x = m.y = m.z = m.w = -__int_as_float(0x7f800000);  // -inf

    // Steady state: 15 chunks. Consume slot i, immediately prefetch the same
    // slot from the next chunk (constant offset from pl), max, store.
#pragma unroll 1
    for (int c = 0; c < NCHUNK - 1; c++) {
#pragma unroll
        for (int i = 0; i < D; i++) {
            float4 x = v[i];
            v[i] = __ldcs(pl - (long long)i * HS);
            m = fmax4(m, x);
            __stcs(q - (long long)i * HS, m);
        }
        pl -= (long long)D * HS;
        q -= (long long)D * HS;
    }

    // Drain: last chunk (h = D-1 .. 0), stores only.
#pragma unroll
    for (int i = 0; i < D; i++) {
        m = fmax4(m, v[i]);
        __stcs(q - (long long)i * HS, m);
    }
}

extern "C" void kernel_launch(void* const* d_in, const int* in_sizes, int n_in,
                              void* d_out, int out_size) {
    const float4* in = (const float4*)d_in[0];
    float4* out = (float4*)d_out;
    int threads = 64;
    int blocks = NCOLS / threads;  // 2048
    revcummax_kernel<<<blocks, threads>>>(in, out);
}

// round 11
// speedup vs baseline: 1.0392x; 1.0392x over previous
#include <cuda_runtime.h>

// Reverse cummax along axis 1 of [B=16, H=128, W=128, C=256] float32.
// out[b,h,w,c] = max over h' >= h of in[b,h',w,c].
//
// R10: identical dataflow to R4/R2 (interleaved prefetch ring, D=8, which
// profiles at DRAM 76% / 80.4us), with ONE change: stores use default
// write-back policy instead of __stcs. Rationale: stores drain via L2
// writeback; evict-first (.stcs) forces early fragmented writebacks that
// interleave against the read stream at the HBM controller. Default policy
// lets dirty lines accumulate in the 126MB L2 and flush in larger bursts.
// Reads stay evict-first (__ldcs) — they are use-once.

#define B 16
#define H 128
#define HS 8192               // h-stride in float4 (W*C/4)
#define NCOLS (B * HS)        // 131072 columns
#define D 8                   // ring depth
#define NCHUNK (H / D)        // 16

__device__ __forceinline__ float4 fmax4(float4 a, float4 b) {
    float4 r;
    r.x = fmaxf(a.x, b.x);
    r.y = fmaxf(a.y, b.y);
    r.z = fmaxf(a.z, b.z);
    r.w = fmaxf(a.w, b.w);
    return r;
}

__global__ __launch_bounds__(64) void revcummax_kernel(
    const float4* __restrict__ in, float4* __restrict__ out) {
    int idx = blockIdx.x * blockDim.x + threadIdx.x;

    int b = idx >> 13;           // / HS
    int inner = idx & (HS - 1);
    long long base = (long long)b * H * (long long)HS + inner;

    // Cursors point at the TOP of the current chunk (highest h of the chunk).
    const float4* pl = in + base + (H - 1) * (long long)HS;
    float4* q = out + base + (H - 1) * (long long)HS;

    // Prologue: fill the ring with h = H-1 .. H-D (immediate offsets).
    float4 v[D];
#pragma unroll
    for (int i = 0; i < D; i++)
        v[i] = __ldcs(pl - (long long)i * HS);
    pl -= (long long)D * HS;

    float4 m;
    m.x = m.y = m.z = m.w = -__int_as_float(0x7f800000);  // -inf

    // Steady state: 15 chunks. Consume slot i, immediately prefetch the same
    // slot from the next chunk (constant offset from pl), max, store.
#pragma unroll 1
    for (int c = 0; c < NCHUNK - 1; c++) {
#pragma unroll
        for (int i = 0; i < D; i++) {
            float4 x = v[i];
            v[i] = __ldcs(pl - (long long)i * HS);
            m = fmax4(m, x);
            *(q - (long long)i * HS) = m;   // default write-back store
        }
        pl -= (long long)D * HS;
        q -= (long long)D * HS;
    }

    // Drain: last chunk (h = D-1 .. 0), stores only.
#pragma unroll
    for (int i = 0; i < D; i++) {
        m = fmax4(m, v[i]);
        *(q - (long long)i * HS) = m;
    }
}

extern "C" void kernel_launch(void* const* d_in, const int* in_sizes, int n_in,
                              void* d_out, int out_size) {
    const float4* in = (const float4*)d_in[0];
    float4* out = (float4*)d_out;
    int threads = 64;
    int blocks = NCOLS / threads;  // 2048
    revcummax_kernel<<<blocks, threads>>>(in, out);
}